// round 1
// baseline (speedup 1.0000x reference)
#include <cuda_runtime.h>
#include <math.h>

// Problem constants
#define BATCH 512
#define IDIM  2048
#define HDIM  2048
#define BH    (BATCH * HDIM)   // 1,048,576

// GEMM tiling
#define BM 128
#define BN 128
#define BK 16
#define TM 8
#define TN 8
// 256 threads = 16x16 thread tile grid

// Scratch for gate pre-activations: Z[4][B][H] = 16 MB
__device__ float g_Z[4u * BATCH * HDIM];

__global__ __launch_bounds__(256, 2)
void gemm4_gates(const float* __restrict__ X,   // inputs  [B, I]
                 const float* __restrict__ S,   // prevstate [B, H]
                 const float* __restrict__ Wi, const float* __restrict__ Ui,
                 const float* __restrict__ Wf, const float* __restrict__ Uf,
                 const float* __restrict__ Wg, const float* __restrict__ Ug,
                 const float* __restrict__ Wc, const float* __restrict__ Uc)
{
    const int gate = blockIdx.z;
    const float* Wm;
    const float* Um;
    switch (gate) {
        case 0:  Wm = Wi; Um = Ui; break;
        case 1:  Wm = Wf; Um = Uf; break;
        case 2:  Wm = Wg; Um = Ug; break;
        default: Wm = Wc; Um = Uc; break;
    }

    const int bm = blockIdx.y * BM;   // batch-row offset
    const int bn = blockIdx.x * BN;   // hidden-col offset

    __shared__ float As[BK][BM];      // A transposed: As[k][m]
    __shared__ float Bs[BK][BN];      // Bs[k][n]

    const int tid = threadIdx.x;
    const int tx = tid & 15;          // 0..15 -> N direction
    const int ty = tid >> 4;          // 0..15 -> M direction

    float acc[TM][TN];
    #pragma unroll
    for (int i = 0; i < TM; i++)
        #pragma unroll
        for (int j = 0; j < TN; j++)
            acc[i][j] = 0.0f;

    // Two phases: (X, W) over K=2048, then (S, U) over K=2048.
    #pragma unroll 1
    for (int phase = 0; phase < 2; phase++) {
        const float* A  = phase ? S  : X;
        const float* Bm = phase ? Um : Wm;

        #pragma unroll 1
        for (int k0 = 0; k0 < 2048; k0 += BK) {
            // ---- Load A tile: 128 rows x 16 cols (512 float4, 2 per thread),
            // store transposed into As[k][m].
            #pragma unroll
            for (int t = 0; t < 2; t++) {
                int idx = tid + t * 256;
                int row = idx >> 2;            // 0..127
                int cg  = (idx & 3) * 4;       // 0,4,8,12
                float4 v = *reinterpret_cast<const float4*>(
                    &A[(size_t)(bm + row) * 2048 + k0 + cg]);
                As[cg + 0][row] = v.x;
                As[cg + 1][row] = v.y;
                As[cg + 2][row] = v.z;
                As[cg + 3][row] = v.w;
            }
            // ---- Load B tile: 16 rows x 128 cols (512 float4, 2 per thread)
            #pragma unroll
            for (int t = 0; t < 2; t++) {
                int idx = tid + t * 256;
                int row = idx >> 5;            // 0..15
                int c4  = (idx & 31) * 4;      // 0..124
                *reinterpret_cast<float4*>(&Bs[row][c4]) =
                    *reinterpret_cast<const float4*>(
                        &Bm[(size_t)(k0 + row) * 2048 + bn + c4]);
            }
            __syncthreads();

            // ---- Compute
            #pragma unroll
            for (int k = 0; k < BK; k++) {
                float a[TM], b[TN];
                *reinterpret_cast<float4*>(&a[0]) =
                    *reinterpret_cast<const float4*>(&As[k][ty * TM]);
                *reinterpret_cast<float4*>(&a[4]) =
                    *reinterpret_cast<const float4*>(&As[k][ty * TM + 4]);
                *reinterpret_cast<float4*>(&b[0]) =
                    *reinterpret_cast<const float4*>(&Bs[k][tx * TN]);
                *reinterpret_cast<float4*>(&b[4]) =
                    *reinterpret_cast<const float4*>(&Bs[k][tx * TN + 4]);
                #pragma unroll
                for (int i = 0; i < TM; i++)
                    #pragma unroll
                    for (int j = 0; j < TN; j++)
                        acc[i][j] = fmaf(a[i], b[j], acc[i][j]);
            }
            __syncthreads();
        }
    }

    // ---- Store Z
    float* Zg = &g_Z[(size_t)gate * BH];
    #pragma unroll
    for (int i = 0; i < TM; i++) {
        int m = bm + ty * TM + i;
        #pragma unroll
        for (int j = 0; j < TN; j += 4) {
            int n = bn + tx * TN + j;
            float4 v = make_float4(acc[i][j], acc[i][j+1], acc[i][j+2], acc[i][j+3]);
            *reinterpret_cast<float4*>(&Zg[(size_t)m * HDIM + n]) = v;
        }
    }
}

__device__ __forceinline__ float sigmoidf_(float x) {
    return 1.0f / (1.0f + __expf(-x));
}

__global__ void lstm_epilogue(const float* __restrict__ bi,
                              const float* __restrict__ bf,
                              const float* __restrict__ bg,
                              const float* __restrict__ bc,
                              const float* __restrict__ prevout, // states[1]
                              float* __restrict__ out, int out_size)
{
    int idx = blockIdx.x * blockDim.x + threadIdx.x;
    if (idx >= BH) return;
    int h = idx & (HDIM - 1);

    float zi = g_Z[0 * BH + idx] + bi[h];
    float zf = g_Z[1 * BH + idx] + bf[h];
    float zg = g_Z[2 * BH + idx] + bg[h];
    float zc = g_Z[3 * BH + idx] + bc[h];

    float ig = sigmoidf_(zi);
    float fg = sigmoidf_(zf);
    float gg = sigmoidf_(zg);   // NOTE: reference uses sigmoid for g (quirk)
    float cc = tanhf(zc);

    float c = fg * prevout[idx] + ig * cc;
    float state = gg * tanhf(c);

    // Output: reference returns (c, stack([state, c])).
    if (out_size >= 3 * BH) {
        out[idx]          = c;
        out[BH + idx]     = state;
        out[2 * BH + idx] = c;
    } else if (out_size >= 2 * BH) {
        out[idx]      = state;
        out[BH + idx] = c;
    } else {
        out[idx] = c;
    }
}

extern "C" void kernel_launch(void* const* d_in, const int* in_sizes, int n_in,
                              void* d_out, int out_size)
{
    const float* inputs = (const float*)d_in[0];   // [B, I]
    const float* states = (const float*)d_in[1];   // [2, B, H]
    const float* Wi = (const float*)d_in[2];
    const float* Ui = (const float*)d_in[3];
    const float* bi = (const float*)d_in[4];
    const float* Wf = (const float*)d_in[5];
    const float* Uf = (const float*)d_in[6];
    const float* bf = (const float*)d_in[7];
    const float* Wg = (const float*)d_in[8];
    const float* Ug = (const float*)d_in[9];
    const float* bg = (const float*)d_in[10];
    const float* Wc = (const float*)d_in[11];
    const float* Uc = (const float*)d_in[12];
    const float* bc = (const float*)d_in[13];

    const float* prevstate = states;        // states[0]
    const float* prevout   = states + BH;   // states[1]

    dim3 grid(HDIM / BN, BATCH / BM, 4);    // (16, 4, 4) = 256 blocks
    gemm4_gates<<<grid, 256>>>(inputs, prevstate,
                               Wi, Ui, Wf, Uf, Wg, Ug, Wc, Uc);

    lstm_epilogue<<<(BH + 255) / 256, 256>>>(bi, bf, bg, bc, prevout,
                                             (float*)d_out, out_size);
}

// round 3
// speedup vs baseline: 2.4825x; 2.4825x over previous
#include <cuda_runtime.h>
#include <cuda_bf16.h>
#include <math.h>
#include <stdint.h>

// ---------------- problem constants ----------------
#define BATCH 512
#define HDIM  2048
#define BH    (BATCH * HDIM)       // 1,048,576
#define ACT   (BATCH * HDIM)
#define WELEM (2048 * 2048)
#define KTOT  4096

// ---------------- GEMM tiling ----------------
#define BM 128
#define BN 128
#define BK 32
#define NITER (KTOT / BK)          // 128

// smem layout (bf16 elems): A padded stride 40, B padded stride 136
#define A_STRIDE 40
#define B_STRIDE 136
#define A_TILE_B (128 * A_STRIDE * 2)   // 10240 B
#define B_TILE_B (BK * B_STRIDE * 2)    // 8704 B
#define OFF_AH 0
#define OFF_AL (A_TILE_B)
#define OFF_BH (2 * A_TILE_B)
#define OFF_BL (2 * A_TILE_B + B_TILE_B)
#define STAGE_B (2 * A_TILE_B + 2 * B_TILE_B)   // 37888
#define DYN_SMEM (2 * STAGE_B)                  // 75776

// ---------------- device scratch ----------------
__device__ float g_Z[4ull * BH];                      // 16 MB
__device__ __nv_bfloat16 g_Ah[2ull * ACT];            // [phase][B][2048]
__device__ __nv_bfloat16 g_Al[2ull * ACT];
__device__ __nv_bfloat16 g_Bh[8ull * WELEM];          // [gate*2+phase][K][N]
__device__ __nv_bfloat16 g_Bl[8ull * WELEM];

// ---------------- PTX helpers ----------------
__device__ __forceinline__ uint32_t s2u(const void* p) {
    uint32_t a;
    asm("{ .reg .u64 t; cvta.to.shared.u64 t, %1; cvt.u32.u64 %0, t; }"
        : "=r"(a) : "l"(p));
    return a;
}
__device__ __forceinline__ void cp16(uint32_t dst, const void* src) {
    asm volatile("cp.async.cg.shared.global [%0], [%1], 16;" :: "r"(dst), "l"(src));
}
#define LDSM4(R, addr)                                                        \
    asm volatile("ldmatrix.sync.aligned.m8n8.x4.shared.b16 {%0,%1,%2,%3}, [%4];" \
                 : "=r"((R)[0]), "=r"((R)[1]), "=r"((R)[2]), "=r"((R)[3])     \
                 : "r"(addr))
#define LDSM4T(R, addr)                                                       \
    asm volatile("ldmatrix.sync.aligned.m8n8.x4.trans.shared.b16 {%0,%1,%2,%3}, [%4];" \
                 : "=r"((R)[0]), "=r"((R)[1]), "=r"((R)[2]), "=r"((R)[3])     \
                 : "r"(addr))
#define MMA(D, A, B0, B1)                                                     \
    asm volatile("mma.sync.aligned.m16n8k16.row.col.f32.bf16.bf16.f32 "        \
                 "{%0,%1,%2,%3},{%4,%5,%6,%7},{%8,%9},{%0,%1,%2,%3};"          \
                 : "+f"((D)[0]), "+f"((D)[1]), "+f"((D)[2]), "+f"((D)[3])     \
                 : "r"((A)[0]), "r"((A)[1]), "r"((A)[2]), "r"((A)[3]),        \
                   "r"(B0), "r"(B1))

// ---------------- conversion kernels ----------------
__global__ void convert_acts(const float* __restrict__ X,
                             const float* __restrict__ S) {
    size_t i4 = ((size_t)blockIdx.x * blockDim.x + threadIdx.x) * 4;
    const float* src = (i4 < ACT) ? (X + i4) : (S + (i4 - ACT));
    float4 v = *reinterpret_cast<const float4*>(src);
    __nv_bfloat16 h[4], l[4];
    float vv[4] = {v.x, v.y, v.z, v.w};
    #pragma unroll
    for (int j = 0; j < 4; j++) {
        h[j] = __float2bfloat16(vv[j]);
        l[j] = __float2bfloat16(vv[j] - __bfloat162float(h[j]));
    }
    *reinterpret_cast<uint2*>(&g_Ah[i4]) = *reinterpret_cast<uint2*>(h);
    *reinterpret_cast<uint2*>(&g_Al[i4]) = *reinterpret_cast<uint2*>(l);
}

__global__ void convert_w(const float* Wi, const float* Ui,
                          const float* Wf, const float* Uf,
                          const float* Wg, const float* Ug,
                          const float* Wc, const float* Uc) {
    int mat = blockIdx.y;
    const float* src;
    switch (mat) {
        case 0: src = Wi; break; case 1: src = Ui; break;
        case 2: src = Wf; break; case 3: src = Uf; break;
        case 4: src = Wg; break; case 5: src = Ug; break;
        case 6: src = Wc; break; default: src = Uc; break;
    }
    size_t i4 = ((size_t)blockIdx.x * blockDim.x + threadIdx.x) * 4;
    size_t o = (size_t)mat * WELEM + i4;
    float4 v = *reinterpret_cast<const float4*>(src + i4);
    __nv_bfloat16 h[4], l[4];
    float vv[4] = {v.x, v.y, v.z, v.w};
    #pragma unroll
    for (int j = 0; j < 4; j++) {
        h[j] = __float2bfloat16(vv[j]);
        l[j] = __float2bfloat16(vv[j] - __bfloat162float(h[j]));
    }
    *reinterpret_cast<uint2*>(&g_Bh[o]) = *reinterpret_cast<uint2*>(h);
    *reinterpret_cast<uint2*>(&g_Bl[o]) = *reinterpret_cast<uint2*>(l);
}

// ---------------- mma.sync GEMM ----------------
__device__ __forceinline__ void prefetch(uint32_t stage, int tid,
                                         int gate, int bm, int bn, int c) {
    int k0 = c * BK;
    int phase = k0 >> 11;
    int kk = k0 & 2047;
    const __nv_bfloat16* A_h = g_Ah + (size_t)phase * ACT + (size_t)bm * 2048 + kk;
    const __nv_bfloat16* A_l = g_Al + (size_t)phase * ACT + (size_t)bm * 2048 + kk;
    size_t bo = (size_t)(gate * 2 + phase) * WELEM + (size_t)kk * 2048 + bn;
    const __nv_bfloat16* B_h = g_Bh + bo;
    const __nv_bfloat16* B_l = g_Bl + bo;

    // A tiles: 128 rows x 64B = 512 chunks; 2 per thread per tile
    #pragma unroll
    for (int t = 0; t < 2; t++) {
        int cid = tid + t * 256;
        int r = cid >> 2, cc = cid & 3;
        uint32_t so = (uint32_t)(r * (A_STRIDE * 2) + cc * 16);
        size_t go = (size_t)r * 2048 + cc * 8;
        cp16(stage + OFF_AH + so, A_h + go);
        cp16(stage + OFF_AL + so, A_l + go);
    }
    // B tiles: 32 rows x 256B = 512 chunks; 2 per thread per tile
    #pragma unroll
    for (int t = 0; t < 2; t++) {
        int cid = tid + t * 256;
        int r = cid >> 4, cc = cid & 15;
        uint32_t so = (uint32_t)(r * (B_STRIDE * 2) + cc * 16);
        size_t go = (size_t)r * 2048 + cc * 8;
        cp16(stage + OFF_BH + so, B_h + go);
        cp16(stage + OFF_BL + so, B_l + go);
    }
}

__global__ __launch_bounds__(256, 2) void gemm_mma() {
    extern __shared__ char smem[];
    const uint32_t sb = s2u(smem);
    const int tid  = threadIdx.x;
    const int gate = blockIdx.z;
    const int bm   = blockIdx.y * BM;
    const int bn   = blockIdx.x * BN;

    const int warp = tid >> 5;
    const int lane = tid & 31;
    const int wm = warp >> 2;        // 0..1 -> m offset 64*wm
    const int wn = warp & 3;         // 0..3 -> n offset 32*wn

    // ldmatrix lane address components
    const int lr  = lane & 15;             // row within 16
    const int lc8 = (lane >> 4) * 8;       // 0 or 8 (second 8-col block)

    float acc[4][4][4];
    #pragma unroll
    for (int i = 0; i < 4; i++)
        #pragma unroll
        for (int j = 0; j < 4; j++)
            #pragma unroll
            for (int k = 0; k < 4; k++) acc[i][j][k] = 0.0f;

    // per-lane smem byte offsets (relative to tile base)
    // A: row-major [128][A_STRIDE]; atom rows = m, col byte = k*2
    uint32_t a_lane = (uint32_t)((wm * 64 + lr) * (A_STRIDE * 2) + lc8 * 2);
    // B: row-major [BK][B_STRIDE]; atom rows = k, col byte = n*2 (trans)
    uint32_t b_lane = (uint32_t)(lr * (B_STRIDE * 2) + (wn * 32 + lc8) * 2);

    prefetch(sb, tid, gate, bm, bn, 0);
    asm volatile("cp.async.commit_group;" ::: "memory");

    #pragma unroll 1
    for (int c = 0; c < NITER; c++) {
        asm volatile("cp.async.wait_group 0;" ::: "memory");
        __syncthreads();
        if (c + 1 < NITER)
            prefetch(sb + (uint32_t)((c + 1) & 1) * STAGE_B, tid, gate, bm, bn, c + 1);
        asm volatile("cp.async.commit_group;" ::: "memory");

        uint32_t st = sb + (uint32_t)(c & 1) * STAGE_B;
        #pragma unroll
        for (int kf = 0; kf < 2; kf++) {
            uint32_t aoff = st + a_lane + (uint32_t)(kf * 32);             // kf*16 elems
            uint32_t boff = st + b_lane + (uint32_t)(kf * 16 * B_STRIDE * 2);

            uint32_t ah[4][4], al[4][4], bh[2][4], bl[2][4];
            #pragma unroll
            for (int mf = 0; mf < 4; mf++)
                LDSM4(ah[mf], aoff + OFF_AH + (uint32_t)(mf * 16 * A_STRIDE * 2));
            #pragma unroll
            for (int nf2 = 0; nf2 < 2; nf2++)
                LDSM4T(bh[nf2], boff + OFF_BH + (uint32_t)(nf2 * 32));

            // hi * hi
            #pragma unroll
            for (int mf = 0; mf < 4; mf++)
                #pragma unroll
                for (int nf = 0; nf < 4; nf++)
                    MMA(acc[mf][nf], ah[mf], bh[nf >> 1][(nf & 1) * 2],
                        bh[nf >> 1][(nf & 1) * 2 + 1]);

            #pragma unroll
            for (int nf2 = 0; nf2 < 2; nf2++)
                LDSM4T(bl[nf2], boff + OFF_BL + (uint32_t)(nf2 * 32));
            // hi * lo
            #pragma unroll
            for (int mf = 0; mf < 4; mf++)
                #pragma unroll
                for (int nf = 0; nf < 4; nf++)
                    MMA(acc[mf][nf], ah[mf], bl[nf >> 1][(nf & 1) * 2],
                        bl[nf >> 1][(nf & 1) * 2 + 1]);

            #pragma unroll
            for (int mf = 0; mf < 4; mf++)
                LDSM4(al[mf], aoff + OFF_AL + (uint32_t)(mf * 16 * A_STRIDE * 2));
            // lo * hi
            #pragma unroll
            for (int mf = 0; mf < 4; mf++)
                #pragma unroll
                for (int nf = 0; nf < 4; nf++)
                    MMA(acc[mf][nf], al[mf], bh[nf >> 1][(nf & 1) * 2],
                        bh[nf >> 1][(nf & 1) * 2 + 1]);
        }
        __syncthreads();
    }

    // store accumulators to g_Z
    float* Zg = g_Z + (size_t)gate * BH;
    const int gr = lane >> 2;        // group row 0..7
    const int gc = (lane & 3) * 2;   // col pair
    #pragma unroll
    for (int mf = 0; mf < 4; mf++) {
        #pragma unroll
        for (int nf = 0; nf < 4; nf++) {
            int row = bm + wm * 64 + mf * 16 + gr;
            int col = bn + wn * 32 + nf * 8 + gc;
            *reinterpret_cast<float2*>(&Zg[(size_t)row * HDIM + col]) =
                make_float2(acc[mf][nf][0], acc[mf][nf][1]);
            *reinterpret_cast<float2*>(&Zg[(size_t)(row + 8) * HDIM + col]) =
                make_float2(acc[mf][nf][2], acc[mf][nf][3]);
        }
    }
}

// ---------------- fused gate epilogue ----------------
__device__ __forceinline__ float sigmoidf_(float x) {
    return 1.0f / (1.0f + __expf(-x));
}

__global__ void lstm_epilogue(const float* __restrict__ bi,
                              const float* __restrict__ bf,
                              const float* __restrict__ bg,
                              const float* __restrict__ bc,
                              const float* __restrict__ prevout,
                              float* __restrict__ out, int out_size) {
    int idx = blockIdx.x * blockDim.x + threadIdx.x;
    if (idx >= BH) return;
    int h = idx & (HDIM - 1);

    float zi = g_Z[0 * (size_t)BH + idx] + bi[h];
    float zf = g_Z[1 * (size_t)BH + idx] + bf[h];
    float zg = g_Z[2 * (size_t)BH + idx] + bg[h];
    float zc = g_Z[3 * (size_t)BH + idx] + bc[h];

    float ig = sigmoidf_(zi);
    float fg = sigmoidf_(zf);
    float gg = sigmoidf_(zg);   // reference quirk: sigmoid for g
    float cc = tanhf(zc);

    float c = fg * prevout[idx] + ig * cc;
    float state = gg * tanhf(c);

    if (out_size >= 3 * BH) {
        out[idx]          = c;
        out[BH + idx]     = state;
        out[2 * BH + idx] = c;
    } else if (out_size >= 2 * BH) {
        out[idx]      = state;
        out[BH + idx] = c;
    } else {
        out[idx] = c;
    }
}

// ---------------- launcher ----------------
extern "C" void kernel_launch(void* const* d_in, const int* in_sizes, int n_in,
                              void* d_out, int out_size) {
    const float* inputs = (const float*)d_in[0];
    const float* states = (const float*)d_in[1];
    const float* Wi = (const float*)d_in[2];
    const float* Ui = (const float*)d_in[3];
    const float* bi = (const float*)d_in[4];
    const float* Wf = (const float*)d_in[5];
    const float* Uf = (const float*)d_in[6];
    const float* bf = (const float*)d_in[7];
    const float* Wg = (const float*)d_in[8];
    const float* Ug = (const float*)d_in[9];
    const float* bg = (const float*)d_in[10];
    const float* Wc = (const float*)d_in[11];
    const float* Uc = (const float*)d_in[12];
    const float* bc = (const float*)d_in[13];

    const float* prevstate = states;        // states[0]
    const float* prevout   = states + BH;   // states[1]

    cudaFuncSetAttribute(gemm_mma, cudaFuncAttributeMaxDynamicSharedMemorySize,
                         DYN_SMEM);

    convert_acts<<<(2 * ACT) / (256 * 4), 256>>>(inputs, prevstate);

    dim3 wgrid(WELEM / (256 * 4), 8);
    convert_w<<<wgrid, 256>>>(Wi, Ui, Wf, Uf, Wg, Ug, Wc, Uc);

    dim3 ggrid(HDIM / BN, BATCH / BM, 4);   // (16, 4, 4) = 256 CTAs
    gemm_mma<<<ggrid, 256, DYN_SMEM>>>();

    lstm_epilogue<<<(BH + 255) / 256, 256>>>(bi, bf, bg, bc, prevout,
                                             (float*)d_out, out_size);
}

// round 4
// speedup vs baseline: 3.3034x; 1.3306x over previous
#include <cuda_runtime.h>
#include <cuda_fp16.h>
#include <math.h>
#include <stdint.h>

// ---------------- problem constants ----------------
#define BATCH 512
#define HDIM  2048
#define BH    (BATCH * HDIM)       // 1,048,576
#define ACT   (BATCH * HDIM)
#define WELEM (2048 * 2048)
#define KTOT  4096

// ---------------- GEMM tiling ----------------
#define BM 128
#define BN 128
#define BK 32
#define NITER (KTOT / BK)          // 128

// smem layout (fp16 elems): A padded stride 40, B padded stride 136
#define A_STRIDE 40
#define B_STRIDE 136
#define A_TILE_B (128 * A_STRIDE * 2)   // 10240 B
#define B_TILE_B (BK * B_STRIDE * 2)    // 8704 B
#define OFF_AH 0
#define OFF_AL (A_TILE_B)
#define OFF_BH (2 * A_TILE_B)
#define STAGE_B (2 * A_TILE_B + B_TILE_B)   // 29184
#define DYN_SMEM (2 * STAGE_B)              // 58368

// ---------------- device scratch ----------------
__device__ float g_Z[4ull * BH];                 // 16 MB
__device__ __half g_Ah[2ull * ACT];              // [phase][B][2048] fp16 hi
__device__ __half g_Al[2ull * ACT];              // fp16 lo (x - hi, exact)
__device__ __half g_Bh[8ull * WELEM];            // [gate*2+phase][K][N] fp16

// ---------------- PTX helpers ----------------
__device__ __forceinline__ uint32_t s2u(const void* p) {
    uint32_t a;
    asm("{ .reg .u64 t; cvta.to.shared.u64 t, %1; cvt.u32.u64 %0, t; }"
        : "=r"(a) : "l"(p));
    return a;
}
__device__ __forceinline__ void cp16(uint32_t dst, const void* src) {
    asm volatile("cp.async.cg.shared.global [%0], [%1], 16;" :: "r"(dst), "l"(src));
}
#define LDSM4(R, addr)                                                        \
    asm volatile("ldmatrix.sync.aligned.m8n8.x4.shared.b16 {%0,%1,%2,%3}, [%4];" \
                 : "=r"((R)[0]), "=r"((R)[1]), "=r"((R)[2]), "=r"((R)[3])     \
                 : "r"(addr))
#define LDSM4T(R, addr)                                                       \
    asm volatile("ldmatrix.sync.aligned.m8n8.x4.trans.shared.b16 {%0,%1,%2,%3}, [%4];" \
                 : "=r"((R)[0]), "=r"((R)[1]), "=r"((R)[2]), "=r"((R)[3])     \
                 : "r"(addr))
#define MMA(D, A, B0, B1)                                                     \
    asm volatile("mma.sync.aligned.m16n8k16.row.col.f32.f16.f16.f32 "          \
                 "{%0,%1,%2,%3},{%4,%5,%6,%7},{%8,%9},{%0,%1,%2,%3};"          \
                 : "+f"((D)[0]), "+f"((D)[1]), "+f"((D)[2]), "+f"((D)[3])     \
                 : "r"((A)[0]), "r"((A)[1]), "r"((A)[2]), "r"((A)[3]),        \
                   "r"(B0), "r"(B1))

// ---------------- conversion kernels ----------------
__global__ void convert_acts(const float* __restrict__ X,
                             const float* __restrict__ S) {
    size_t i4 = ((size_t)blockIdx.x * blockDim.x + threadIdx.x) * 4;
    const float* src = (i4 < ACT) ? (X + i4) : (S + (i4 - ACT));
    float4 v = *reinterpret_cast<const float4*>(src);
    __half h[4], l[4];
    float vv[4] = {v.x, v.y, v.z, v.w};
    #pragma unroll
    for (int j = 0; j < 4; j++) {
        h[j] = __float2half(vv[j]);
        l[j] = __float2half(vv[j] - __half2float(h[j]));
    }
    *reinterpret_cast<uint2*>(&g_Ah[i4]) = *reinterpret_cast<uint2*>(h);
    *reinterpret_cast<uint2*>(&g_Al[i4]) = *reinterpret_cast<uint2*>(l);
}

__global__ void convert_w(const float* Wi, const float* Ui,
                          const float* Wf, const float* Uf,
                          const float* Wg, const float* Ug,
                          const float* Wc, const float* Uc) {
    int mat = blockIdx.y;
    const float* src;
    switch (mat) {
        case 0: src = Wi; break; case 1: src = Ui; break;
        case 2: src = Wf; break; case 3: src = Uf; break;
        case 4: src = Wg; break; case 5: src = Ug; break;
        case 6: src = Wc; break; default: src = Uc; break;
    }
    size_t i4 = ((size_t)blockIdx.x * blockDim.x + threadIdx.x) * 4;
    size_t o = (size_t)mat * WELEM + i4;
    float4 v = *reinterpret_cast<const float4*>(src + i4);
    __half h[4];
    h[0] = __float2half(v.x); h[1] = __float2half(v.y);
    h[2] = __float2half(v.z); h[3] = __float2half(v.w);
    *reinterpret_cast<uint2*>(&g_Bh[o]) = *reinterpret_cast<uint2*>(h);
}

// ---------------- mma.sync GEMM ----------------
__device__ __forceinline__ void prefetch(uint32_t stage, int tid,
                                         int gate, int bm, int bn, int c) {
    int k0 = c * BK;
    int phase = k0 >> 11;
    int kk = k0 & 2047;
    const __half* A_h = g_Ah + (size_t)phase * ACT + (size_t)bm * 2048 + kk;
    const __half* A_l = g_Al + (size_t)phase * ACT + (size_t)bm * 2048 + kk;
    const __half* B_h = g_Bh + (size_t)(gate * 2 + phase) * WELEM
                             + (size_t)kk * 2048 + bn;

    // A tiles: 128 rows x 64B = 512 chunks; 2 per thread per tile
    #pragma unroll
    for (int t = 0; t < 2; t++) {
        int cid = tid + t * 256;
        int r = cid >> 2, cc = cid & 3;
        uint32_t so = (uint32_t)(r * (A_STRIDE * 2) + cc * 16);
        size_t go = (size_t)r * 2048 + cc * 8;
        cp16(stage + OFF_AH + so, A_h + go);
        cp16(stage + OFF_AL + so, A_l + go);
    }
    // B tile: 32 rows x 256B = 512 chunks; 2 per thread
    #pragma unroll
    for (int t = 0; t < 2; t++) {
        int cid = tid + t * 256;
        int r = cid >> 4, cc = cid & 15;
        uint32_t so = (uint32_t)(r * (B_STRIDE * 2) + cc * 16);
        size_t go = (size_t)r * 2048 + cc * 8;
        cp16(stage + OFF_BH + so, B_h + go);
    }
}

__global__ __launch_bounds__(256, 2) void gemm_mma() {
    extern __shared__ char smem[];
    const uint32_t sb = s2u(smem);
    const int tid  = threadIdx.x;
    const int gate = blockIdx.z;
    const int bm   = blockIdx.y * BM;
    const int bn   = blockIdx.x * BN;

    const int warp = tid >> 5;
    const int lane = tid & 31;
    const int wm = warp >> 2;        // 0..1 -> m offset 64*wm
    const int wn = warp & 3;         // 0..3 -> n offset 32*wn

    const int lr  = lane & 15;
    const int lc8 = (lane >> 4) * 8;

    float acc[4][4][4];
    #pragma unroll
    for (int i = 0; i < 4; i++)
        #pragma unroll
        for (int j = 0; j < 4; j++)
            #pragma unroll
            for (int k = 0; k < 4; k++) acc[i][j][k] = 0.0f;

    uint32_t a_lane = (uint32_t)((wm * 64 + lr) * (A_STRIDE * 2) + lc8 * 2);
    uint32_t b_lane = (uint32_t)(lr * (B_STRIDE * 2) + (wn * 32 + lc8) * 2);

    prefetch(sb, tid, gate, bm, bn, 0);
    asm volatile("cp.async.commit_group;" ::: "memory");

    #pragma unroll 1
    for (int c = 0; c < NITER; c++) {
        asm volatile("cp.async.wait_group 0;" ::: "memory");
        __syncthreads();
        if (c + 1 < NITER)
            prefetch(sb + (uint32_t)((c + 1) & 1) * STAGE_B, tid, gate, bm, bn, c + 1);
        asm volatile("cp.async.commit_group;" ::: "memory");

        uint32_t st = sb + (uint32_t)(c & 1) * STAGE_B;
        #pragma unroll
        for (int kf = 0; kf < 2; kf++) {
            uint32_t aoff = st + a_lane + (uint32_t)(kf * 32);
            uint32_t boff = st + b_lane + (uint32_t)(kf * 16 * B_STRIDE * 2);

            uint32_t ah[4][4], al[4][4], bh[2][4];
            #pragma unroll
            for (int mf = 0; mf < 4; mf++)
                LDSM4(ah[mf], aoff + OFF_AH + (uint32_t)(mf * 16 * A_STRIDE * 2));
            #pragma unroll
            for (int nf2 = 0; nf2 < 2; nf2++)
                LDSM4T(bh[nf2], boff + OFF_BH + (uint32_t)(nf2 * 32));

            // hi * w
            #pragma unroll
            for (int mf = 0; mf < 4; mf++)
                #pragma unroll
                for (int nf = 0; nf < 4; nf++)
                    MMA(acc[mf][nf], ah[mf], bh[nf >> 1][(nf & 1) * 2],
                        bh[nf >> 1][(nf & 1) * 2 + 1]);

            #pragma unroll
            for (int mf = 0; mf < 4; mf++)
                LDSM4(al[mf], aoff + OFF_AL + (uint32_t)(mf * 16 * A_STRIDE * 2));

            // lo * w  (together: exact x * fp16(w))
            #pragma unroll
            for (int mf = 0; mf < 4; mf++)
                #pragma unroll
                for (int nf = 0; nf < 4; nf++)
                    MMA(acc[mf][nf], al[mf], bh[nf >> 1][(nf & 1) * 2],
                        bh[nf >> 1][(nf & 1) * 2 + 1]);
        }
        __syncthreads();
    }

    // store accumulators to g_Z
    float* Zg = g_Z + (size_t)gate * BH;
    const int gr = lane >> 2;
    const int gc = (lane & 3) * 2;
    #pragma unroll
    for (int mf = 0; mf < 4; mf++) {
        #pragma unroll
        for (int nf = 0; nf < 4; nf++) {
            int row = bm + wm * 64 + mf * 16 + gr;
            int col = bn + wn * 32 + nf * 8 + gc;
            *reinterpret_cast<float2*>(&Zg[(size_t)row * HDIM + col]) =
                make_float2(acc[mf][nf][0], acc[mf][nf][1]);
            *reinterpret_cast<float2*>(&Zg[(size_t)(row + 8) * HDIM + col]) =
                make_float2(acc[mf][nf][2], acc[mf][nf][3]);
        }
    }
}

// ---------------- fused gate epilogue ----------------
__device__ __forceinline__ float sigmoidf_(float x) {
    return 1.0f / (1.0f + __expf(-x));
}

__global__ void lstm_epilogue(const float* __restrict__ bi,
                              const float* __restrict__ bf,
                              const float* __restrict__ bg,
                              const float* __restrict__ bc,
                              const float* __restrict__ prevout,
                              float* __restrict__ out, int out_size) {
    int idx = blockIdx.x * blockDim.x + threadIdx.x;
    if (idx >= BH) return;
    int h = idx & (HDIM - 1);

    float zi = g_Z[0 * (size_t)BH + idx] + bi[h];
    float zf = g_Z[1 * (size_t)BH + idx] + bf[h];
    float zg = g_Z[2 * (size_t)BH + idx] + bg[h];
    float zc = g_Z[3 * (size_t)BH + idx] + bc[h];

    float ig = sigmoidf_(zi);
    float fg = sigmoidf_(zf);
    float gg = sigmoidf_(zg);   // reference quirk: sigmoid for g
    float cc = tanhf(zc);

    float c = fg * prevout[idx] + ig * cc;
    float state = gg * tanhf(c);

    if (out_size >= 3 * BH) {
        out[idx]          = c;
        out[BH + idx]     = state;
        out[2 * BH + idx] = c;
    } else if (out_size >= 2 * BH) {
        out[idx]      = state;
        out[BH + idx] = c;
    } else {
        out[idx] = c;
    }
}

// ---------------- launcher ----------------
extern "C" void kernel_launch(void* const* d_in, const int* in_sizes, int n_in,
                              void* d_out, int out_size) {
    const float* inputs = (const float*)d_in[0];
    const float* states = (const float*)d_in[1];
    const float* Wi = (const float*)d_in[2];
    const float* Ui = (const float*)d_in[3];
    const float* bi = (const float*)d_in[4];
    const float* Wf = (const float*)d_in[5];
    const float* Uf = (const float*)d_in[6];
    const float* bf = (const float*)d_in[7];
    const float* Wg = (const float*)d_in[8];
    const float* Ug = (const float*)d_in[9];
    const float* bg = (const float*)d_in[10];
    const float* Wc = (const float*)d_in[11];
    const float* Uc = (const float*)d_in[12];
    const float* bc = (const float*)d_in[13];

    const float* prevstate = states;        // states[0]
    const float* prevout   = states + BH;   // states[1]

    cudaFuncSetAttribute(gemm_mma, cudaFuncAttributeMaxDynamicSharedMemorySize,
                         DYN_SMEM);

    convert_acts<<<(2 * ACT) / (256 * 4), 256>>>(inputs, prevstate);

    dim3 wgrid(WELEM / (256 * 4), 8);
    convert_w<<<wgrid, 256>>>(Wi, Ui, Wf, Uf, Wg, Ug, Wc, Uc);

    dim3 ggrid(HDIM / BN, BATCH / BM, 4);   // (16, 4, 4) = 256 CTAs
    gemm_mma<<<ggrid, 256, DYN_SMEM>>>();

    lstm_epilogue<<<(BH + 255) / 256, 256>>>(bi, bf, bg, bc, prevout,
                                             (float*)d_out, out_size);
}

// round 5
// speedup vs baseline: 5.3558x; 1.6213x over previous
#include <cuda_runtime.h>
#include <cuda_fp16.h>
#include <math.h>
#include <stdint.h>

// ---------------- problem constants ----------------
#define BATCH 512
#define HDIM  2048
#define BH    (BATCH * HDIM)       // 1,048,576
#define ACT   (BATCH * HDIM)
#define WELEM (2048 * 2048)
#define KTOT  4096

// ---------------- GEMM tiling ----------------
#define BM 128
#define BN 128
#define BK 32
#define NITER (KTOT / BK)          // 128

// smem layout (fp16 elems): A padded stride 40, B padded stride 136
#define A_STRIDE 40
#define B_STRIDE 136
#define A_TILE_B (128 * A_STRIDE * 2)   // 10240 B
#define B_TILE_B (BK * B_STRIDE * 2)    // 8704 B
#define OFF_A 0
#define OFF_B (A_TILE_B)
#define STAGE_B (A_TILE_B + B_TILE_B)   // 18944
#define NSTAGE 3
#define DYN_SMEM (NSTAGE * STAGE_B)     // 56832

// ---------------- device scratch ----------------
__device__ float g_Z[4ull * BH];                 // 16 MB
__device__ __half g_A[2ull * ACT];               // [phase][B][2048] fp16
__device__ __half g_B[8ull * WELEM];             // [gate*2+phase][K][N] fp16

// ---------------- PTX helpers ----------------
__device__ __forceinline__ uint32_t s2u(const void* p) {
    uint32_t a;
    asm("{ .reg .u64 t; cvta.to.shared.u64 t, %1; cvt.u32.u64 %0, t; }"
        : "=r"(a) : "l"(p));
    return a;
}
__device__ __forceinline__ void cp16(uint32_t dst, const void* src) {
    asm volatile("cp.async.cg.shared.global [%0], [%1], 16;" :: "r"(dst), "l"(src));
}
#define LDSM4(R, addr)                                                        \
    asm volatile("ldmatrix.sync.aligned.m8n8.x4.shared.b16 {%0,%1,%2,%3}, [%4];" \
                 : "=r"((R)[0]), "=r"((R)[1]), "=r"((R)[2]), "=r"((R)[3])     \
                 : "r"(addr))
#define LDSM4T(R, addr)                                                       \
    asm volatile("ldmatrix.sync.aligned.m8n8.x4.trans.shared.b16 {%0,%1,%2,%3}, [%4];" \
                 : "=r"((R)[0]), "=r"((R)[1]), "=r"((R)[2]), "=r"((R)[3])     \
                 : "r"(addr))
#define MMA(D, A, B0, B1)                                                     \
    asm volatile("mma.sync.aligned.m16n8k16.row.col.f32.f16.f16.f32 "          \
                 "{%0,%1,%2,%3},{%4,%5,%6,%7},{%8,%9},{%0,%1,%2,%3};"          \
                 : "+f"((D)[0]), "+f"((D)[1]), "+f"((D)[2]), "+f"((D)[3])     \
                 : "r"((A)[0]), "r"((A)[1]), "r"((A)[2]), "r"((A)[3]),        \
                   "r"(B0), "r"(B1))

// ---------------- conversion kernels ----------------
__global__ void convert_acts(const float* __restrict__ X,
                             const float* __restrict__ S) {
    size_t i4 = ((size_t)blockIdx.x * blockDim.x + threadIdx.x) * 4;
    const float* src = (i4 < ACT) ? (X + i4) : (S + (i4 - ACT));
    float4 v = *reinterpret_cast<const float4*>(src);
    __half h[4];
    h[0] = __float2half(v.x); h[1] = __float2half(v.y);
    h[2] = __float2half(v.z); h[3] = __float2half(v.w);
    *reinterpret_cast<uint2*>(&g_A[i4]) = *reinterpret_cast<uint2*>(h);
}

__global__ void convert_w(const float* Wi, const float* Ui,
                          const float* Wf, const float* Uf,
                          const float* Wg, const float* Ug,
                          const float* Wc, const float* Uc) {
    int mat = blockIdx.y;
    const float* src;
    switch (mat) {
        case 0: src = Wi; break; case 1: src = Ui; break;
        case 2: src = Wf; break; case 3: src = Uf; break;
        case 4: src = Wg; break; case 5: src = Ug; break;
        case 6: src = Wc; break; default: src = Uc; break;
    }
    size_t i4 = ((size_t)blockIdx.x * blockDim.x + threadIdx.x) * 4;
    size_t o = (size_t)mat * WELEM + i4;
    float4 v = *reinterpret_cast<const float4*>(src + i4);
    __half h[4];
    h[0] = __float2half(v.x); h[1] = __float2half(v.y);
    h[2] = __float2half(v.z); h[3] = __float2half(v.w);
    *reinterpret_cast<uint2*>(&g_B[o]) = *reinterpret_cast<uint2*>(h);
}

// ---------------- mma.sync GEMM ----------------
__device__ __forceinline__ void prefetch(uint32_t stage, int tid,
                                         int gate, int bm, int bn, int c) {
    int k0 = c * BK;
    int phase = k0 >> 11;
    int kk = k0 & 2047;
    const __half* A_p = g_A + (size_t)phase * ACT + (size_t)bm * 2048 + kk;
    const __half* B_p = g_B + (size_t)(gate * 2 + phase) * WELEM
                            + (size_t)kk * 2048 + bn;

    // A tile: 128 rows x 64B = 512 chunks; 2 per thread
    #pragma unroll
    for (int t = 0; t < 2; t++) {
        int cid = tid + t * 256;
        int r = cid >> 2, cc = cid & 3;
        uint32_t so = (uint32_t)(r * (A_STRIDE * 2) + cc * 16);
        size_t go = (size_t)r * 2048 + cc * 8;
        cp16(stage + OFF_A + so, A_p + go);
    }
    // B tile: 32 rows x 256B = 512 chunks; 2 per thread
    #pragma unroll
    for (int t = 0; t < 2; t++) {
        int cid = tid + t * 256;
        int r = cid >> 4, cc = cid & 15;
        uint32_t so = (uint32_t)(r * (B_STRIDE * 2) + cc * 16);
        size_t go = (size_t)r * 2048 + cc * 8;
        cp16(stage + OFF_B + so, B_p + go);
    }
}

__global__ __launch_bounds__(256, 2) void gemm_mma() {
    extern __shared__ char smem[];
    const uint32_t sb = s2u(smem);
    const int tid  = threadIdx.x;
    const int gate = blockIdx.z;
    const int bm   = blockIdx.y * BM;
    const int bn   = blockIdx.x * BN;

    const int warp = tid >> 5;
    const int lane = tid & 31;
    const int wm = warp >> 2;        // 0..1 -> m offset 64*wm
    const int wn = warp & 3;         // 0..3 -> n offset 32*wn

    const int lr  = lane & 15;
    const int lc8 = (lane >> 4) * 8;

    float acc[4][4][4];
    #pragma unroll
    for (int i = 0; i < 4; i++)
        #pragma unroll
        for (int j = 0; j < 4; j++)
            #pragma unroll
            for (int k = 0; k < 4; k++) acc[i][j][k] = 0.0f;

    uint32_t a_lane = (uint32_t)((wm * 64 + lr) * (A_STRIDE * 2) + lc8 * 2);
    uint32_t b_lane = (uint32_t)(lr * (B_STRIDE * 2) + (wn * 32 + lc8) * 2);

    // 3-stage prologue
    prefetch(sb + 0 * STAGE_B, tid, gate, bm, bn, 0);
    asm volatile("cp.async.commit_group;" ::: "memory");
    prefetch(sb + 1 * STAGE_B, tid, gate, bm, bn, 1);
    asm volatile("cp.async.commit_group;" ::: "memory");

    uint32_t buf = 0;   // stage index of chunk c
    #pragma unroll 1
    for (int c = 0; c < NITER; c++) {
        asm volatile("cp.async.wait_group 1;" ::: "memory");
        __syncthreads();

        if (c + 2 < NITER) {
            uint32_t nbuf = buf + 2;
            if (nbuf >= NSTAGE) nbuf -= NSTAGE;
            prefetch(sb + nbuf * STAGE_B, tid, gate, bm, bn, c + 2);
        }
        asm volatile("cp.async.commit_group;" ::: "memory");

        uint32_t st = sb + buf * STAGE_B;
        #pragma unroll
        for (int kf = 0; kf < 2; kf++) {
            uint32_t aoff = st + OFF_A + a_lane + (uint32_t)(kf * 32);
            uint32_t boff = st + OFF_B + b_lane + (uint32_t)(kf * 16 * B_STRIDE * 2);

            uint32_t ar[4][4], br[2][4];
            #pragma unroll
            for (int mf = 0; mf < 4; mf++)
                LDSM4(ar[mf], aoff + (uint32_t)(mf * 16 * A_STRIDE * 2));
            #pragma unroll
            for (int nf2 = 0; nf2 < 2; nf2++)
                LDSM4T(br[nf2], boff + (uint32_t)(nf2 * 32));

            #pragma unroll
            for (int mf = 0; mf < 4; mf++)
                #pragma unroll
                for (int nf = 0; nf < 4; nf++)
                    MMA(acc[mf][nf], ar[mf], br[nf >> 1][(nf & 1) * 2],
                        br[nf >> 1][(nf & 1) * 2 + 1]);
        }
        __syncthreads();

        buf = (buf + 1 == NSTAGE) ? 0 : buf + 1;
    }

    // store accumulators to g_Z
    float* Zg = g_Z + (size_t)gate * BH;
    const int gr = lane >> 2;
    const int gc = (lane & 3) * 2;
    #pragma unroll
    for (int mf = 0; mf < 4; mf++) {
        #pragma unroll
        for (int nf = 0; nf < 4; nf++) {
            int row = bm + wm * 64 + mf * 16 + gr;
            int col = bn + wn * 32 + nf * 8 + gc;
            *reinterpret_cast<float2*>(&Zg[(size_t)row * HDIM + col]) =
                make_float2(acc[mf][nf][0], acc[mf][nf][1]);
            *reinterpret_cast<float2*>(&Zg[(size_t)(row + 8) * HDIM + col]) =
                make_float2(acc[mf][nf][2], acc[mf][nf][3]);
        }
    }
}

// ---------------- fused gate epilogue ----------------
__device__ __forceinline__ float sigmoidf_(float x) {
    return 1.0f / (1.0f + __expf(-x));
}

__global__ void lstm_epilogue(const float* __restrict__ bi,
                              const float* __restrict__ bf,
                              const float* __restrict__ bg,
                              const float* __restrict__ bc,
                              const float* __restrict__ prevout,
                              float* __restrict__ out, int out_size) {
    int idx = blockIdx.x * blockDim.x + threadIdx.x;
    if (idx >= BH) return;
    int h = idx & (HDIM - 1);

    float zi = g_Z[0 * (size_t)BH + idx] + bi[h];
    float zf = g_Z[1 * (size_t)BH + idx] + bf[h];
    float zg = g_Z[2 * (size_t)BH + idx] + bg[h];
    float zc = g_Z[3 * (size_t)BH + idx] + bc[h];

    float ig = sigmoidf_(zi);
    float fg = sigmoidf_(zf);
    float gg = sigmoidf_(zg);   // reference quirk: sigmoid for g
    float cc = tanhf(zc);

    float c = fg * prevout[idx] + ig * cc;
    float state = gg * tanhf(c);

    if (out_size >= 3 * BH) {
        out[idx]          = c;
        out[BH + idx]     = state;
        out[2 * BH + idx] = c;
    } else if (out_size >= 2 * BH) {
        out[idx]      = state;
        out[BH + idx] = c;
    } else {
        out[idx] = c;
    }
}

// ---------------- launcher ----------------
extern "C" void kernel_launch(void* const* d_in, const int* in_sizes, int n_in,
                              void* d_out, int out_size) {
    const float* inputs = (const float*)d_in[0];
    const float* states = (const float*)d_in[1];
    const float* Wi = (const float*)d_in[2];
    const float* Ui = (const float*)d_in[3];
    const float* bi = (const float*)d_in[4];
    const float* Wf = (const float*)d_in[5];
    const float* Uf = (const float*)d_in[6];
    const float* bf = (const float*)d_in[7];
    const float* Wg = (const float*)d_in[8];
    const float* Ug = (const float*)d_in[9];
    const float* bg = (const float*)d_in[10];
    const float* Wc = (const float*)d_in[11];
    const float* Uc = (const float*)d_in[12];
    const float* bc = (const float*)d_in[13];

    const float* prevstate = states;        // states[0]
    const float* prevout   = states + BH;   // states[1]

    cudaFuncSetAttribute(gemm_mma, cudaFuncAttributeMaxDynamicSharedMemorySize,
                         DYN_SMEM);

    convert_acts<<<(2 * ACT) / (256 * 4), 256>>>(inputs, prevstate);

    dim3 wgrid(WELEM / (256 * 4), 8);
    convert_w<<<wgrid, 256>>>(Wi, Ui, Wf, Uf, Wg, Ug, Wc, Uc);

    dim3 ggrid(HDIM / BN, BATCH / BM, 4);   // (16, 4, 4) = 256 CTAs
    gemm_mma<<<ggrid, 256, DYN_SMEM>>>();

    lstm_epilogue<<<(BH + 255) / 256, 256>>>(bi, bf, bg, bc, prevout,
                                             (float*)d_out, out_size);
}

// round 6
// speedup vs baseline: 6.0148x; 1.1230x over previous
#include <cuda_runtime.h>
#include <cuda_fp16.h>
#include <math.h>
#include <stdint.h>

// ---------------- problem constants ----------------
#define BATCH 512
#define HDIM  2048
#define BH    (BATCH * HDIM)       // 1,048,576
#define ACT   (BATCH * HDIM)
#define WELEM (2048 * 2048)
#define KTOT  4096

// ---------------- GEMM tiling ----------------
#define BM 128
#define BN 128
#define BK 32
#define NITER (KTOT / BK)          // 128

// smem layout (fp16 elems): A padded stride 40, B padded stride 136
#define A_STRIDE 40
#define B_STRIDE 136
#define A_TILE_B (128 * A_STRIDE * 2)   // 10240 B
#define B_TILE_B (BK * B_STRIDE * 2)    // 8704 B
#define OFF_A 0
#define OFF_B (A_TILE_B)
#define STAGE_B (A_TILE_B + B_TILE_B)   // 18944
#define NSTAGE 3
#define DYN_SMEM (NSTAGE * STAGE_B)     // 56832

// ---------------- device scratch ----------------
__device__ float g_Z[4ull * BH];                 // 16 MB
__device__ __half g_A[2ull * ACT];               // [phase][B][2048] fp16
__device__ __half g_B[8ull * WELEM];             // [gate*2+phase][K][N] fp16

// ---------------- PTX helpers ----------------
__device__ __forceinline__ uint32_t s2u(const void* p) {
    uint32_t a;
    asm("{ .reg .u64 t; cvta.to.shared.u64 t, %1; cvt.u32.u64 %0, t; }"
        : "=r"(a) : "l"(p));
    return a;
}
__device__ __forceinline__ void cp16(uint32_t dst, const void* src) {
    asm volatile("cp.async.cg.shared.global [%0], [%1], 16;" :: "r"(dst), "l"(src));
}
#define LDSM4(R, addr)                                                        \
    asm volatile("ldmatrix.sync.aligned.m8n8.x4.shared.b16 {%0,%1,%2,%3}, [%4];" \
                 : "=r"((R)[0]), "=r"((R)[1]), "=r"((R)[2]), "=r"((R)[3])     \
                 : "r"(addr))
#define LDSM4T(R, addr)                                                       \
    asm volatile("ldmatrix.sync.aligned.m8n8.x4.trans.shared.b16 {%0,%1,%2,%3}, [%4];" \
                 : "=r"((R)[0]), "=r"((R)[1]), "=r"((R)[2]), "=r"((R)[3])     \
                 : "r"(addr))
#define MMA(D, A, B0, B1)                                                     \
    asm volatile("mma.sync.aligned.m16n8k16.row.col.f32.f16.f16.f32 "          \
                 "{%0,%1,%2,%3},{%4,%5,%6,%7},{%8,%9},{%0,%1,%2,%3};"          \
                 : "+f"((D)[0]), "+f"((D)[1]), "+f"((D)[2]), "+f"((D)[3])     \
                 : "r"((A)[0]), "r"((A)[1]), "r"((A)[2]), "r"((A)[3]),        \
                   "r"(B0), "r"(B1))

// ---------------- conversion kernels ----------------
__global__ void convert_acts(const float* __restrict__ X,
                             const float* __restrict__ S) {
    size_t i4 = ((size_t)blockIdx.x * blockDim.x + threadIdx.x) * 4;
    const float* src = (i4 < ACT) ? (X + i4) : (S + (i4 - ACT));
    float4 v = *reinterpret_cast<const float4*>(src);
    __half h[4];
    h[0] = __float2half(v.x); h[1] = __float2half(v.y);
    h[2] = __float2half(v.z); h[3] = __float2half(v.w);
    *reinterpret_cast<uint2*>(&g_A[i4]) = *reinterpret_cast<uint2*>(h);
}

__global__ void convert_w(const float* Wi, const float* Ui,
                          const float* Wf, const float* Uf,
                          const float* Wg, const float* Ug,
                          const float* Wc, const float* Uc) {
    int mat = blockIdx.y;
    const float* src;
    switch (mat) {
        case 0: src = Wi; break; case 1: src = Ui; break;
        case 2: src = Wf; break; case 3: src = Uf; break;
        case 4: src = Wg; break; case 5: src = Ug; break;
        case 6: src = Wc; break; default: src = Uc; break;
    }
    size_t i4 = ((size_t)blockIdx.x * blockDim.x + threadIdx.x) * 4;
    size_t o = (size_t)mat * WELEM + i4;
    float4 v = *reinterpret_cast<const float4*>(src + i4);
    __half h[4];
    h[0] = __float2half(v.x); h[1] = __float2half(v.y);
    h[2] = __float2half(v.z); h[3] = __float2half(v.w);
    *reinterpret_cast<uint2*>(&g_B[o]) = *reinterpret_cast<uint2*>(h);
}

// ---------------- mma.sync GEMM (128 threads, 4 warps of 64x64) ----------------
__device__ __forceinline__ void prefetch(uint32_t stage, int tid,
                                         int gate, int bm, int bn, int c) {
    int k0 = c * BK;
    int phase = k0 >> 11;
    int kk = k0 & 2047;
    const __half* A_p = g_A + (size_t)phase * ACT + (size_t)bm * 2048 + kk;
    const __half* B_p = g_B + (size_t)(gate * 2 + phase) * WELEM
                            + (size_t)kk * 2048 + bn;

    // A tile: 128 rows x 4 chunks(16B) = 512; 4 per thread
    #pragma unroll
    for (int t = 0; t < 4; t++) {
        int cid = tid + t * 128;
        int r = cid >> 2, cc = cid & 3;
        uint32_t so = (uint32_t)(r * (A_STRIDE * 2) + cc * 16);
        size_t go = (size_t)r * 2048 + cc * 8;
        cp16(stage + OFF_A + so, A_p + go);
    }
    // B tile: 32 rows x 16 chunks = 512; 4 per thread
    #pragma unroll
    for (int t = 0; t < 4; t++) {
        int cid = tid + t * 128;
        int r = cid >> 4, cc = cid & 15;
        uint32_t so = (uint32_t)(r * (B_STRIDE * 2) + cc * 16);
        size_t go = (size_t)r * 2048 + cc * 8;
        cp16(stage + OFF_B + so, B_p + go);
    }
}

__global__ __launch_bounds__(128, 2) void gemm_mma() {
    extern __shared__ char smem[];
    const uint32_t sb = s2u(smem);
    const int tid  = threadIdx.x;
    const int gate = blockIdx.z;
    const int bm   = blockIdx.y * BM;
    const int bn   = blockIdx.x * BN;

    const int warp = tid >> 5;
    const int lane = tid & 31;
    const int wm = warp >> 1;        // 0..1 -> m offset 64*wm
    const int wn = warp & 1;         // 0..1 -> n offset 64*wn

    const int lr  = lane & 15;
    const int lc8 = (lane >> 4) * 8;

    float acc[4][8][4];
    #pragma unroll
    for (int i = 0; i < 4; i++)
        #pragma unroll
        for (int j = 0; j < 8; j++)
            #pragma unroll
            for (int k = 0; k < 4; k++) acc[i][j][k] = 0.0f;

    uint32_t a_lane = (uint32_t)((wm * 64 + lr) * (A_STRIDE * 2) + lc8 * 2);
    uint32_t b_lane = (uint32_t)(lr * (B_STRIDE * 2) + (wn * 64 + lc8) * 2);

    // 3-stage prologue
    prefetch(sb + 0 * STAGE_B, tid, gate, bm, bn, 0);
    asm volatile("cp.async.commit_group;" ::: "memory");
    prefetch(sb + 1 * STAGE_B, tid, gate, bm, bn, 1);
    asm volatile("cp.async.commit_group;" ::: "memory");

    uint32_t buf = 0;   // stage index of chunk c
    #pragma unroll 1
    for (int c = 0; c < NITER; c++) {
        asm volatile("cp.async.wait_group 1;" ::: "memory");
        __syncthreads();

        if (c + 2 < NITER) {
            uint32_t nbuf = buf + 2;
            if (nbuf >= NSTAGE) nbuf -= NSTAGE;
            prefetch(sb + nbuf * STAGE_B, tid, gate, bm, bn, c + 2);
        }
        asm volatile("cp.async.commit_group;" ::: "memory");

        uint32_t st = sb + buf * STAGE_B;
        #pragma unroll
        for (int kf = 0; kf < 2; kf++) {
            uint32_t aoff = st + OFF_A + a_lane + (uint32_t)(kf * 32);
            uint32_t boff = st + OFF_B + b_lane + (uint32_t)(kf * 16 * B_STRIDE * 2);

            uint32_t ar[4][4], br[4][4];
            #pragma unroll
            for (int mf = 0; mf < 4; mf++)
                LDSM4(ar[mf], aoff + (uint32_t)(mf * 16 * A_STRIDE * 2));
            #pragma unroll
            for (int nf2 = 0; nf2 < 4; nf2++)
                LDSM4T(br[nf2], boff + (uint32_t)(nf2 * 32));

            #pragma unroll
            for (int mf = 0; mf < 4; mf++)
                #pragma unroll
                for (int nf = 0; nf < 8; nf++)
                    MMA(acc[mf][nf], ar[mf], br[nf >> 1][(nf & 1) * 2],
                        br[nf >> 1][(nf & 1) * 2 + 1]);
        }
        __syncthreads();

        buf = (buf + 1 == NSTAGE) ? 0 : buf + 1;
    }

    // store accumulators to g_Z
    float* Zg = g_Z + (size_t)gate * BH;
    const int gr = lane >> 2;
    const int gc = (lane & 3) * 2;
    #pragma unroll
    for (int mf = 0; mf < 4; mf++) {
        #pragma unroll
        for (int nf = 0; nf < 8; nf++) {
            int row = bm + wm * 64 + mf * 16 + gr;
            int col = bn + wn * 64 + nf * 8 + gc;
            *reinterpret_cast<float2*>(&Zg[(size_t)row * HDIM + col]) =
                make_float2(acc[mf][nf][0], acc[mf][nf][1]);
            *reinterpret_cast<float2*>(&Zg[(size_t)(row + 8) * HDIM + col]) =
                make_float2(acc[mf][nf][2], acc[mf][nf][3]);
        }
    }
}

// ---------------- fused gate epilogue ----------------
__device__ __forceinline__ float sigmoidf_(float x) {
    return 1.0f / (1.0f + __expf(-x));
}

__global__ void lstm_epilogue(const float* __restrict__ bi,
                              const float* __restrict__ bf,
                              const float* __restrict__ bg,
                              const float* __restrict__ bc,
                              const float* __restrict__ prevout,
                              float* __restrict__ out, int out_size) {
    int idx = blockIdx.x * blockDim.x + threadIdx.x;
    if (idx >= BH) return;
    int h = idx & (HDIM - 1);

    float zi = g_Z[0 * (size_t)BH + idx] + bi[h];
    float zf = g_Z[1 * (size_t)BH + idx] + bf[h];
    float zg = g_Z[2 * (size_t)BH + idx] + bg[h];
    float zc = g_Z[3 * (size_t)BH + idx] + bc[h];

    float ig = sigmoidf_(zi);
    float fg = sigmoidf_(zf);
    float gg = sigmoidf_(zg);   // reference quirk: sigmoid for g
    float cc = tanhf(zc);

    float c = fg * prevout[idx] + ig * cc;
    float state = gg * tanhf(c);

    if (out_size >= 3 * BH) {
        out[idx]          = c;
        out[BH + idx]     = state;
        out[2 * BH + idx] = c;
    } else if (out_size >= 2 * BH) {
        out[idx]      = state;
        out[BH + idx] = c;
    } else {
        out[idx] = c;
    }
}

// ---------------- launcher ----------------
extern "C" void kernel_launch(void* const* d_in, const int* in_sizes, int n_in,
                              void* d_out, int out_size) {
    const float* inputs = (const float*)d_in[0];
    const float* states = (const float*)d_in[1];
    const float* Wi = (const float*)d_in[2];
    const float* Ui = (const float*)d_in[3];
    const float* bi = (const float*)d_in[4];
    const float* Wf = (const float*)d_in[5];
    const float* Uf = (const float*)d_in[6];
    const float* bf = (const float*)d_in[7];
    const float* Wg = (const float*)d_in[8];
    const float* Ug = (const float*)d_in[9];
    const float* bg = (const float*)d_in[10];
    const float* Wc = (const float*)d_in[11];
    const float* Uc = (const float*)d_in[12];
    const float* bc = (const float*)d_in[13];

    const float* prevstate = states;        // states[0]
    const float* prevout   = states + BH;   // states[1]

    cudaFuncSetAttribute(gemm_mma, cudaFuncAttributeMaxDynamicSharedMemorySize,
                         DYN_SMEM);

    convert_acts<<<(2 * ACT) / (256 * 4), 256>>>(inputs, prevstate);

    dim3 wgrid(WELEM / (256 * 4), 8);
    convert_w<<<wgrid, 256>>>(Wi, Ui, Wf, Uf, Wg, Ug, Wc, Uc);

    dim3 ggrid(HDIM / BN, BATCH / BM, 4);   // (16, 4, 4) = 256 CTAs
    gemm_mma<<<ggrid, 128, DYN_SMEM>>>();

    lstm_epilogue<<<(BH + 255) / 256, 256>>>(bi, bf, bg, bc, prevout,
                                             (float*)d_out, out_size);
}